// round 2
// baseline (speedup 1.0000x reference)
#include <cuda_runtime.h>
#include <math.h>

#define NMAX 50000
#define EMAX 1600000

// ---------------- scratch (device globals; no allocations allowed) ----------
__device__ float g_h   [(size_t)NMAX * 128];   // current layer linear transform
__device__ float g_agg [(size_t)NMAX * 128];   // aggregation accumulator
__device__ float g_tmp [(size_t)NMAX * 128];   // layer1 activated output
__device__ float g_emb [(size_t)NMAX * 128];   // emb scratch (if out has no room)
__device__ float g_as  [NMAX * 2];
__device__ float g_ad  [NMAX * 2];
__device__ float g_emax[NMAX * 2];
__device__ float g_den [NMAX * 2];
__device__ float g_z1  [(size_t)NMAX * 512];
__device__ float g_z2  [(size_t)NMAX * 256];

// ---------------- helpers ----------------------------------------------------
__device__ __forceinline__ float leaky(float v) { return v >= 0.f ? v : 0.2f * v; }

// float atomic max via signed/unsigned monotone bit trick (slot pre-initialized
// with a real float, so representation is always consistent).
__device__ __forceinline__ void atomicMaxF(float* addr, float v) {
    if (v >= 0.f) atomicMax((int*)addr, __float_as_int(v));
    else          atomicMin((unsigned int*)addr, __float_as_uint(v));
}

// ---------------- generic fp32 GEMM: C = act(A[M,K] @ B[K,N] + bias) ---------
// BM=BN=64, BK=16, 256 threads, 4x4 per thread. K multiple of 16, N multiple of 4.
__global__ __launch_bounds__(256) void k_gemm(
    const float* __restrict__ A, const float* __restrict__ B,
    const float* __restrict__ bias, float* __restrict__ C,
    int M, int N, int K, int act)
{
    __shared__ float As[16][68];
    __shared__ float Bs[16][68];
    const int tid = threadIdx.x;
    const int rb = blockIdx.y * 64;
    const int cb = blockIdx.x * 64;
    const int tx = tid & 15;
    const int ty = tid >> 4;
    const int ar = tid >> 2, ak = (tid & 3) * 4;   // A tile load coords
    const int bk = tid >> 4, bc = (tid & 15) * 4;  // B tile load coords
    float acc[4][4] = {};

    for (int k0 = 0; k0 < K; k0 += 16) {
        float4 av = make_float4(0.f, 0.f, 0.f, 0.f);
        if (rb + ar < M)
            av = *(const float4*)(A + (size_t)(rb + ar) * K + k0 + ak);
        As[ak + 0][ar] = av.x; As[ak + 1][ar] = av.y;
        As[ak + 2][ar] = av.z; As[ak + 3][ar] = av.w;

        float4 bv = make_float4(0.f, 0.f, 0.f, 0.f);
        if (cb + bc < N)
            bv = *(const float4*)(B + (size_t)(k0 + bk) * N + cb + bc);
        Bs[bk][bc + 0] = bv.x; Bs[bk][bc + 1] = bv.y;
        Bs[bk][bc + 2] = bv.z; Bs[bk][bc + 3] = bv.w;
        __syncthreads();

        #pragma unroll
        for (int k = 0; k < 16; k++) {
            float4 a4 = *(const float4*)&As[k][ty * 4];
            float4 b4 = *(const float4*)&Bs[k][tx * 4];
            float a[4] = {a4.x, a4.y, a4.z, a4.w};
            float b[4] = {b4.x, b4.y, b4.z, b4.w};
            #pragma unroll
            for (int i = 0; i < 4; i++)
                #pragma unroll
                for (int j = 0; j < 4; j++)
                    acc[i][j] = fmaf(a[i], b[j], acc[i][j]);
        }
        __syncthreads();
    }

    #pragma unroll
    for (int i = 0; i < 4; i++) {
        int r = rb + ty * 4 + i;
        if (r >= M) continue;
        #pragma unroll
        for (int j = 0; j < 4; j++) {
            int c = cb + tx * 4 + j;
            if (c >= N) continue;
            float v = acc[i][j];
            if (bias) v += bias[c];
            if (act)  v = fmaxf(v, 0.f);
            C[(size_t)r * N + c] = v;
        }
    }
}

// ---------------- per-node: attention logits + self-loop max init ------------
// thread = (node, head). as/ad = <h[n,head,:], a_src/a_dst[head,:]>.
__global__ __launch_bounds__(256) void k_node_alpha(
    const float* __restrict__ h, const float* __restrict__ a_src,
    const float* __restrict__ a_dst, float* __restrict__ as_,
    float* __restrict__ ad_, float* __restrict__ emax, int n)
{
    int idx = blockIdx.x * blockDim.x + threadIdx.x;
    if (idx >= 2 * n) return;
    int node = idx >> 1, hd = idx & 1;
    const float4* hp = (const float4*)(h + (size_t)node * 128 + hd * 64);
    const float4* sp = (const float4*)(a_src + hd * 64);
    const float4* dp = (const float4*)(a_dst + hd * 64);
    float sa = 0.f, sd = 0.f;
    #pragma unroll
    for (int i = 0; i < 16; i++) {
        float4 hv = hp[i], sv = sp[i], dv = dp[i];
        sa += hv.x * sv.x + hv.y * sv.y + hv.z * sv.z + hv.w * sv.w;
        sd += hv.x * dv.x + hv.y * dv.y + hv.z * dv.z + hv.w * dv.w;
    }
    as_[idx] = sa;
    ad_[idx] = sd;
    emax[idx] = leaky(sa + sd);   // self-loop score initializes the max
}

// ---------------- edge pass 1: segment max --------------------------------
__global__ __launch_bounds__(256) void k_edge_max(
    const int* __restrict__ ei, const float* __restrict__ as_,
    const float* __restrict__ ad_, float* __restrict__ emax, int nE)
{
    int e = blockIdx.x * blockDim.x + threadIdx.x;
    if (e >= nE) return;
    int s = ei[e], d = ei[nE + e];
    #pragma unroll
    for (int hd = 0; hd < 2; hd++) {
        float v = leaky(as_[s * 2 + hd] + ad_[d * 2 + hd]);
        atomicMaxF(&emax[d * 2 + hd], v);
    }
}

// ---------------- per-node: denom init with self-loop term -------------------
__global__ __launch_bounds__(256) void k_node_den(
    const float* __restrict__ as_, const float* __restrict__ ad_,
    const float* __restrict__ emax, float* __restrict__ den, int n)
{
    int idx = blockIdx.x * blockDim.x + threadIdx.x;
    if (idx >= 2 * n) return;
    float el = leaky(as_[idx] + ad_[idx]);
    den[idx] = expf(el - emax[idx]);
}

// ---------------- edge pass 2: segment denom ---------------------------------
__global__ __launch_bounds__(256) void k_edge_den(
    const int* __restrict__ ei, const float* __restrict__ as_,
    const float* __restrict__ ad_, const float* __restrict__ emax,
    float* __restrict__ den, int nE)
{
    int e = blockIdx.x * blockDim.x + threadIdx.x;
    if (e >= nE) return;
    int s = ei[e], d = ei[nE + e];
    #pragma unroll
    for (int hd = 0; hd < 2; hd++) {
        float v = leaky(as_[s * 2 + hd] + ad_[d * 2 + hd]);
        atomicAdd(&den[d * 2 + hd], expf(v - emax[d * 2 + hd]));
    }
}

// ---------------- per-node: agg init with self-loop message ------------------
// thread = one float4 of one node's 128-dim feature.
__global__ __launch_bounds__(256) void k_node_self(
    const float* __restrict__ h, const float* __restrict__ as_,
    const float* __restrict__ ad_, const float* __restrict__ emax,
    const float* __restrict__ den, float* __restrict__ agg, int n)
{
    int idx = blockIdx.x * blockDim.x + threadIdx.x;
    if (idx >= n * 32) return;
    int node = idx >> 5, c4 = idx & 31;
    int hd = c4 >> 4;
    int a = node * 2 + hd;
    float el = leaky(as_[a] + ad_[a]);
    float w = expf(el - emax[a]) / (den[a] + 1e-16f);
    float4 hv = ((const float4*)h)[idx];
    float4 o = make_float4(hv.x * w, hv.y * w, hv.z * w, hv.w * w);
    ((float4*)agg)[idx] = o;
}

// ---------------- edge pass 3: weighted message scatter (warp per edge) ------
__global__ __launch_bounds__(256) void k_edge_msg(
    const int* __restrict__ ei, const float* __restrict__ h,
    const float* __restrict__ as_, const float* __restrict__ ad_,
    const float* __restrict__ emax, const float* __restrict__ den,
    float* __restrict__ agg, int nE)
{
    int w = (blockIdx.x * blockDim.x + threadIdx.x) >> 5;
    int lane = threadIdx.x & 31;
    if (w >= nE) return;
    int s = ei[w], d = ei[nE + w];
    int hd = lane >> 4;                    // lanes 0-15: head 0, 16-31: head 1
    float e = leaky(as_[s * 2 + hd] + ad_[d * 2 + hd]);
    float wgt = expf(e - emax[d * 2 + hd]) / (den[d * 2 + hd] + 1e-16f);
    float4 hv = *(const float4*)(h + (size_t)s * 128 + lane * 4);
    float* p = agg + (size_t)d * 128 + lane * 4;
    asm volatile("red.global.add.v4.f32 [%0], {%1,%2,%3,%4};"
                 :: "l"(p), "f"(hv.x * wgt), "f"(hv.y * wgt),
                    "f"(hv.z * wgt), "f"(hv.w * wgt)
                 : "memory");
}

// ---------------- per-node: bias + relu --------------------------------------
__global__ __launch_bounds__(256) void k_node_out(
    const float* __restrict__ agg, const float* __restrict__ bias,
    float* __restrict__ out, int n)
{
    int idx = blockIdx.x * blockDim.x + threadIdx.x;
    if (idx >= n * 32) return;
    int c4 = idx & 31;
    float4 v = ((const float4*)agg)[idx];
    float4 b = ((const float4*)bias)[c4];
    v.x = fmaxf(v.x + b.x, 0.f);
    v.y = fmaxf(v.y + b.y, 0.f);
    v.z = fmaxf(v.z + b.z, 0.f);
    v.w = fmaxf(v.w + b.w, 0.f);
    ((float4*)out)[idx] = v;
}

// ---------------- launch ------------------------------------------------------
static void gat_layer(const float* xin, int inK,
                      const float* W, const float* a_s, const float* a_d,
                      const float* b, const int* ei, int n, int e,
                      float* h, float* agg,
                      float* as_, float* ad_, float* emax, float* den,
                      float* out)
{
    k_gemm<<<dim3(2, (n + 63) / 64), 256>>>(xin, W, nullptr, h, n, 128, inK, 0);
    int t2 = 2 * n;
    k_node_alpha<<<(t2 + 255) / 256, 256>>>(h, a_s, a_d, as_, ad_, emax, n);
    k_edge_max<<<(e + 255) / 256, 256>>>(ei, as_, ad_, emax, e);
    k_node_den<<<(t2 + 255) / 256, 256>>>(as_, ad_, emax, den, n);
    k_edge_den<<<(e + 255) / 256, 256>>>(ei, as_, ad_, emax, den, e);
    k_node_self<<<(n * 32 + 255) / 256, 256>>>(h, as_, ad_, emax, den, agg, n);
    long ethreads = (long)e * 32;
    k_edge_msg<<<(unsigned)((ethreads + 255) / 256), 256>>>(ei, h, as_, ad_, emax, den, agg, e);
    k_node_out<<<(n * 32 + 255) / 256, 256>>>(agg, b, out, n);
}

extern "C" void kernel_launch(void* const* d_in, const int* in_sizes, int n_in,
                              void* d_out, int out_size)
{
    const float* x   = (const float*)d_in[0];
    const int*   ei  = (const int*)  d_in[1];
    const float* W1  = (const float*)d_in[2];
    const float* as1 = (const float*)d_in[3];
    const float* ad1 = (const float*)d_in[4];
    const float* b1  = (const float*)d_in[5];
    const float* W2  = (const float*)d_in[6];
    const float* as2 = (const float*)d_in[7];
    const float* ad2 = (const float*)d_in[8];
    const float* b2  = (const float*)d_in[9];
    const float* lw1 = (const float*)d_in[10];
    const float* lb1 = (const float*)d_in[11];
    const float* lw2 = (const float*)d_in[12];
    const float* lb2 = (const float*)d_in[13];
    const float* lw3 = (const float*)d_in[14];
    const float* lb3 = (const float*)d_in[15];
    float* out = (float*)d_out;

    int n = in_sizes[0] / 64;
    int e = in_sizes[1] / 2;

    float *h, *agg, *tmp, *embS, *as_, *ad_, *emax, *den, *z1, *z2;
    cudaGetSymbolAddress((void**)&h,    g_h);
    cudaGetSymbolAddress((void**)&agg,  g_agg);
    cudaGetSymbolAddress((void**)&tmp,  g_tmp);
    cudaGetSymbolAddress((void**)&embS, g_emb);
    cudaGetSymbolAddress((void**)&as_,  g_as);
    cudaGetSymbolAddress((void**)&ad_,  g_ad);
    cudaGetSymbolAddress((void**)&emax, g_emax);
    cudaGetSymbolAddress((void**)&den,  g_den);
    cudaGetSymbolAddress((void**)&z1,   g_z1);
    cudaGetSymbolAddress((void**)&z2,   g_z2);

    // output layout: (emb, logits) concatenated if out has room, else logits only
    float* embPtr;
    float* logitsPtr;
    if ((long)out_size >= (long)n * 144) {
        embPtr = out;
        logitsPtr = out + (size_t)n * 128;
    } else {
        embPtr = embS;
        logitsPtr = out;
    }

    // GAT layer 1: x[ n,64 ] -> tmp[ n,128 ]
    gat_layer(x, 64, W1, as1, ad1, b1, ei, n, e, h, agg, as_, ad_, emax, den, tmp);
    // GAT layer 2: tmp -> emb
    gat_layer(tmp, 128, W2, as2, ad2, b2, ei, n, e, h, agg, as_, ad_, emax, den, embPtr);

    // MLP head
    dim3 gy((unsigned)((n + 63) / 64));
    k_gemm<<<dim3(8, gy.x), 256>>>(embPtr, lw1, lb1, z1, n, 512, 128, 1);
    k_gemm<<<dim3(4, gy.x), 256>>>(z1, lw2, lb2, z2, n, 256, 512, 1);
    k_gemm<<<dim3(1, gy.x), 256>>>(z2, lw3, lb3, logitsPtr, n, 16, 256, 0);
}

// round 3
// speedup vs baseline: 1.4335x; 1.4335x over previous
#include <cuda_runtime.h>
#include <math.h>

#define NMAX 50000
#define EMAX 1600000

// ---------------- scratch (device globals; no allocations allowed) ----------
__device__ float g_h   [(size_t)NMAX * 128];
__device__ float g_agg [(size_t)NMAX * 128];
__device__ float g_tmp [(size_t)NMAX * 128];
__device__ float g_emb [(size_t)NMAX * 128];
__device__ float g_as  [NMAX * 2];
__device__ float g_ad  [NMAX * 2];
__device__ float g_den [NMAX * 2];
__device__ float g_z1  [(size_t)NMAX * 512];
__device__ float g_z2  [(size_t)NMAX * 256];

__device__ __forceinline__ float leaky(float v) { return v >= 0.f ? v : 0.2f * v; }

__device__ __forceinline__ unsigned f2tf32(float f) {
    unsigned r;
    asm("cvt.rna.tf32.f32 %0, %1;" : "=r"(r) : "f"(f));
    return r;
}

// ================= tensor-core tf32 GEMM ====================================
// C[M,N] = act(A[M,K] @ B[K,N] + bias). BM=128, BN=128, BK=16.
// 256 threads = 8 warps in 4(m) x 2(n); warp tile 32x64 via m16n8k8 tf32 mma.
// Requires: K % 16 == 0, N % 128 == 0 (per grid.x tiling). M tail guarded.
#define A_STRIDE 20   // 16 + 4 pad: frag-load conflict-free (20 mod 32 -> distinct)
#define B_STRIDE 136  // 128 + 8 pad: frag-load conflict-free

__global__ __launch_bounds__(256) void k_gemm_tc(
    const float* __restrict__ A, const float* __restrict__ B,
    const float* __restrict__ bias, float* __restrict__ C,
    int M, int N, int K, int act)
{
    __shared__ float As[128 * A_STRIDE];
    __shared__ float Bs[16 * B_STRIDE];

    const int tid  = threadIdx.x;
    const int lane = tid & 31;
    const int wid  = tid >> 5;
    const int rb   = blockIdx.y * 128;
    const int cb   = blockIdx.x * 128;
    const int warpM = (wid & 3) * 32;
    const int warpN = (wid >> 2) * 64;

    const int arow = tid >> 2;          // 0..63 (two halves)
    const int acol = (tid & 3) * 4;
    const int brow = tid >> 5;          // 0..7 (two halves)
    const int bcol = (tid & 31) * 4;

    float acc[2][8][4];
    #pragma unroll
    for (int i = 0; i < 2; i++)
        #pragma unroll
        for (int j = 0; j < 8; j++)
            #pragma unroll
            for (int v = 0; v < 4; v++) acc[i][j][v] = 0.f;

    for (int k0 = 0; k0 < K; k0 += 16) {
        // ---- stage A tile (convert to tf32 bits at store) ----
        #pragma unroll
        for (int h = 0; h < 2; h++) {
            int r = arow + h * 64;
            float4 v = make_float4(0.f, 0.f, 0.f, 0.f);
            if (rb + r < M)
                v = *(const float4*)(A + (size_t)(rb + r) * K + k0 + acol);
            float4 t;
            t.x = __uint_as_float(f2tf32(v.x));
            t.y = __uint_as_float(f2tf32(v.y));
            t.z = __uint_as_float(f2tf32(v.z));
            t.w = __uint_as_float(f2tf32(v.w));
            *(float4*)(As + r * A_STRIDE + acol) = t;
        }
        // ---- stage B tile ----
        #pragma unroll
        for (int h = 0; h < 2; h++) {
            int kr = brow + h * 8;
            float4 v = *(const float4*)(B + (size_t)(k0 + kr) * N + cb + bcol);
            float4 t;
            t.x = __uint_as_float(f2tf32(v.x));
            t.y = __uint_as_float(f2tf32(v.y));
            t.z = __uint_as_float(f2tf32(v.z));
            t.w = __uint_as_float(f2tf32(v.w));
            *(float4*)(Bs + kr * B_STRIDE + bcol) = t;
        }
        __syncthreads();

        #pragma unroll
        for (int ks = 0; ks < 2; ks++) {
            unsigned af[2][4];
            #pragma unroll
            for (int mt = 0; mt < 2; mt++) {
                int r0 = warpM + mt * 16 + (lane >> 2);
                int c0 = ks * 8 + (lane & 3);
                af[mt][0] = __float_as_uint(As[r0 * A_STRIDE + c0]);
                af[mt][1] = __float_as_uint(As[(r0 + 8) * A_STRIDE + c0]);
                af[mt][2] = __float_as_uint(As[r0 * A_STRIDE + c0 + 4]);
                af[mt][3] = __float_as_uint(As[(r0 + 8) * A_STRIDE + c0 + 4]);
            }
            unsigned bf[8][2];
            #pragma unroll
            for (int nt = 0; nt < 8; nt++) {
                int kk = ks * 8 + (lane & 3);
                int nn = warpN + nt * 8 + (lane >> 2);
                bf[nt][0] = __float_as_uint(Bs[kk * B_STRIDE + nn]);
                bf[nt][1] = __float_as_uint(Bs[(kk + 4) * B_STRIDE + nn]);
            }
            #pragma unroll
            for (int mt = 0; mt < 2; mt++)
                #pragma unroll
                for (int nt = 0; nt < 8; nt++) {
                    asm volatile(
                        "mma.sync.aligned.m16n8k8.row.col.f32.tf32.tf32.f32 "
                        "{%0,%1,%2,%3}, {%4,%5,%6,%7}, {%8,%9}, {%0,%1,%2,%3};"
                        : "+f"(acc[mt][nt][0]), "+f"(acc[mt][nt][1]),
                          "+f"(acc[mt][nt][2]), "+f"(acc[mt][nt][3])
                        : "r"(af[mt][0]), "r"(af[mt][1]), "r"(af[mt][2]), "r"(af[mt][3]),
                          "r"(bf[nt][0]), "r"(bf[nt][1]));
                }
        }
        __syncthreads();
    }

    // ---- epilogue: bias + optional relu ----
    #pragma unroll
    for (int mt = 0; mt < 2; mt++) {
        int r0 = rb + warpM + mt * 16 + (lane >> 2);
        #pragma unroll
        for (int nt = 0; nt < 8; nt++) {
            int c0 = cb + warpN + nt * 8 + (lane & 3) * 2;
            float b0 = 0.f, b1 = 0.f;
            if (bias) { b0 = bias[c0]; b1 = bias[c0 + 1]; }
            float v0 = acc[mt][nt][0] + b0;
            float v1 = acc[mt][nt][1] + b1;
            float v2 = acc[mt][nt][2] + b0;
            float v3 = acc[mt][nt][3] + b1;
            if (act) {
                v0 = fmaxf(v0, 0.f); v1 = fmaxf(v1, 0.f);
                v2 = fmaxf(v2, 0.f); v3 = fmaxf(v3, 0.f);
            }
            if (r0 < M) {
                C[(size_t)r0 * N + c0] = v0;
                C[(size_t)r0 * N + c0 + 1] = v1;
            }
            if (r0 + 8 < M) {
                C[(size_t)(r0 + 8) * N + c0] = v2;
                C[(size_t)(r0 + 8) * N + c0 + 1] = v3;
            }
        }
    }
}

// ================= SIMT GEMM (small-N logits only) ===========================
__global__ __launch_bounds__(256) void k_gemm(
    const float* __restrict__ A, const float* __restrict__ B,
    const float* __restrict__ bias, float* __restrict__ C,
    int M, int N, int K, int act)
{
    __shared__ float As[16][68];
    __shared__ float Bs[16][68];
    const int tid = threadIdx.x;
    const int rb = blockIdx.y * 64;
    const int cb = blockIdx.x * 64;
    const int tx = tid & 15;
    const int ty = tid >> 4;
    const int ar = tid >> 2, ak = (tid & 3) * 4;
    const int bk = tid >> 4, bc = (tid & 15) * 4;
    float acc[4][4] = {};

    for (int k0 = 0; k0 < K; k0 += 16) {
        float4 av = make_float4(0.f, 0.f, 0.f, 0.f);
        if (rb + ar < M)
            av = *(const float4*)(A + (size_t)(rb + ar) * K + k0 + ak);
        As[ak + 0][ar] = av.x; As[ak + 1][ar] = av.y;
        As[ak + 2][ar] = av.z; As[ak + 3][ar] = av.w;

        float4 bv = make_float4(0.f, 0.f, 0.f, 0.f);
        if (cb + bc < N)
            bv = *(const float4*)(B + (size_t)(k0 + bk) * N + cb + bc);
        Bs[bk][bc + 0] = bv.x; Bs[bk][bc + 1] = bv.y;
        Bs[bk][bc + 2] = bv.z; Bs[bk][bc + 3] = bv.w;
        __syncthreads();

        #pragma unroll
        for (int k = 0; k < 16; k++) {
            float4 a4 = *(const float4*)&As[k][ty * 4];
            float4 b4 = *(const float4*)&Bs[k][tx * 4];
            float a[4] = {a4.x, a4.y, a4.z, a4.w};
            float b[4] = {b4.x, b4.y, b4.z, b4.w};
            #pragma unroll
            for (int i = 0; i < 4; i++)
                #pragma unroll
                for (int j = 0; j < 4; j++)
                    acc[i][j] = fmaf(a[i], b[j], acc[i][j]);
        }
        __syncthreads();
    }

    #pragma unroll
    for (int i = 0; i < 4; i++) {
        int r = rb + ty * 4 + i;
        if (r >= M) continue;
        #pragma unroll
        for (int j = 0; j < 4; j++) {
            int c = cb + tx * 4 + j;
            if (c >= N) continue;
            float v = acc[i][j];
            if (bias) v += bias[c];
            if (act)  v = fmaxf(v, 0.f);
            C[(size_t)r * N + c] = v;
        }
    }
}

// ---------------- per-node: attention logits + self-loop denom init ----------
// (no segment-max: softmax is shift-invariant; logits are O(1) here)
__global__ __launch_bounds__(256) void k_node_alpha(
    const float* __restrict__ h, const float* __restrict__ a_src,
    const float* __restrict__ a_dst, float* __restrict__ as_,
    float* __restrict__ ad_, float* __restrict__ den, int n)
{
    int idx = blockIdx.x * blockDim.x + threadIdx.x;
    if (idx >= 2 * n) return;
    int node = idx >> 1, hd = idx & 1;
    const float4* hp = (const float4*)(h + (size_t)node * 128 + hd * 64);
    const float4* sp = (const float4*)(a_src + hd * 64);
    const float4* dp = (const float4*)(a_dst + hd * 64);
    float sa = 0.f, sd = 0.f;
    #pragma unroll
    for (int i = 0; i < 16; i++) {
        float4 hv = hp[i], sv = sp[i], dv = dp[i];
        sa += hv.x * sv.x + hv.y * sv.y + hv.z * sv.z + hv.w * sv.w;
        sd += hv.x * dv.x + hv.y * dv.y + hv.z * dv.z + hv.w * dv.w;
    }
    as_[idx] = sa;
    ad_[idx] = sd;
    den[idx] = expf(leaky(sa + sd));   // self-loop term
}

// ---------------- edge pass 1: softmax denominator ---------------------------
__global__ __launch_bounds__(256) void k_edge_den(
    const int* __restrict__ ei, const float* __restrict__ as_,
    const float* __restrict__ ad_, float* __restrict__ den, int nE)
{
    int e = blockIdx.x * blockDim.x + threadIdx.x;
    if (e >= nE) return;
    int s = ei[e], d = ei[nE + e];
    float2 vs = *(const float2*)(as_ + s * 2);
    float2 vd = *(const float2*)(ad_ + d * 2);
    float e0 = expf(leaky(vs.x + vd.x));
    float e1 = expf(leaky(vs.y + vd.y));
    asm volatile("red.global.add.v2.f32 [%0], {%1,%2};"
                 :: "l"(den + d * 2), "f"(e0), "f"(e1) : "memory");
}

// ---------------- per-node: agg init with self-loop message ------------------
__global__ __launch_bounds__(256) void k_node_self(
    const float* __restrict__ h, const float* __restrict__ as_,
    const float* __restrict__ ad_, const float* __restrict__ den,
    float* __restrict__ agg, int n)
{
    int idx = blockIdx.x * blockDim.x + threadIdx.x;
    if (idx >= n * 32) return;
    int node = idx >> 5, c4 = idx & 31;
    int hd = c4 >> 4;
    int a = node * 2 + hd;
    float w = expf(leaky(as_[a] + ad_[a])) / (den[a] + 1e-16f);
    float4 hv = ((const float4*)h)[idx];
    ((float4*)agg)[idx] = make_float4(hv.x * w, hv.y * w, hv.z * w, hv.w * w);
}

// ---------------- edge pass 2: weighted message scatter (warp per edge) ------
__global__ __launch_bounds__(256) void k_edge_msg(
    const int* __restrict__ ei, const float* __restrict__ h,
    const float* __restrict__ as_, const float* __restrict__ ad_,
    const float* __restrict__ den, float* __restrict__ agg, int nE)
{
    int w = (blockIdx.x * blockDim.x + threadIdx.x) >> 5;
    int lane = threadIdx.x & 31;
    if (w >= nE) return;
    int s = ei[w], d = ei[nE + w];
    int hd = lane >> 4;
    float e = leaky(as_[s * 2 + hd] + ad_[d * 2 + hd]);
    float wgt = expf(e) / (den[d * 2 + hd] + 1e-16f);
    float4 hv = *(const float4*)(h + (size_t)s * 128 + lane * 4);
    float* p = agg + (size_t)d * 128 + lane * 4;
    asm volatile("red.global.add.v4.f32 [%0], {%1,%2,%3,%4};"
                 :: "l"(p), "f"(hv.x * wgt), "f"(hv.y * wgt),
                    "f"(hv.z * wgt), "f"(hv.w * wgt)
                 : "memory");
}

// ---------------- per-node: bias + relu --------------------------------------
__global__ __launch_bounds__(256) void k_node_out(
    const float* __restrict__ agg, const float* __restrict__ bias,
    float* __restrict__ out, int n)
{
    int idx = blockIdx.x * blockDim.x + threadIdx.x;
    if (idx >= n * 32) return;
    int c4 = idx & 31;
    float4 v = ((const float4*)agg)[idx];
    float4 b = ((const float4*)bias)[c4];
    v.x = fmaxf(v.x + b.x, 0.f);
    v.y = fmaxf(v.y + b.y, 0.f);
    v.z = fmaxf(v.z + b.z, 0.f);
    v.w = fmaxf(v.w + b.w, 0.f);
    ((float4*)out)[idx] = v;
}

// ---------------- launch ------------------------------------------------------
static void gat_layer(const float* xin, int inK,
                      const float* W, const float* a_s, const float* a_d,
                      const float* b, const int* ei, int n, int e,
                      float* h, float* agg,
                      float* as_, float* ad_, float* den,
                      float* out)
{
    k_gemm_tc<<<dim3(1, (n + 127) / 128), 256>>>(xin, W, nullptr, h, n, 128, inK, 0);
    int t2 = 2 * n;
    k_node_alpha<<<(t2 + 255) / 256, 256>>>(h, a_s, a_d, as_, ad_, den, n);
    k_edge_den<<<(e + 255) / 256, 256>>>(ei, as_, ad_, den, e);
    k_node_self<<<(n * 32 + 255) / 256, 256>>>(h, as_, ad_, den, agg, n);
    long ethreads = (long)e * 32;
    k_edge_msg<<<(unsigned)((ethreads + 255) / 256), 256>>>(ei, h, as_, ad_, den, agg, e);
    k_node_out<<<(n * 32 + 255) / 256, 256>>>(agg, b, out, n);
}

extern "C" void kernel_launch(void* const* d_in, const int* in_sizes, int n_in,
                              void* d_out, int out_size)
{
    const float* x   = (const float*)d_in[0];
    const int*   ei  = (const int*)  d_in[1];
    const float* W1  = (const float*)d_in[2];
    const float* as1 = (const float*)d_in[3];
    const float* ad1 = (const float*)d_in[4];
    const float* b1  = (const float*)d_in[5];
    const float* W2  = (const float*)d_in[6];
    const float* as2 = (const float*)d_in[7];
    const float* ad2 = (const float*)d_in[8];
    const float* b2  = (const float*)d_in[9];
    const float* lw1 = (const float*)d_in[10];
    const float* lb1 = (const float*)d_in[11];
    const float* lw2 = (const float*)d_in[12];
    const float* lb2 = (const float*)d_in[13];
    const float* lw3 = (const float*)d_in[14];
    const float* lb3 = (const float*)d_in[15];
    float* out = (float*)d_out;

    int n = in_sizes[0] / 64;
    int e = in_sizes[1] / 2;

    float *h, *agg, *tmp, *embS, *as_, *ad_, *den, *z1, *z2;
    cudaGetSymbolAddress((void**)&h,    g_h);
    cudaGetSymbolAddress((void**)&agg,  g_agg);
    cudaGetSymbolAddress((void**)&tmp,  g_tmp);
    cudaGetSymbolAddress((void**)&embS, g_emb);
    cudaGetSymbolAddress((void**)&as_,  g_as);
    cudaGetSymbolAddress((void**)&ad_,  g_ad);
    cudaGetSymbolAddress((void**)&den,  g_den);
    cudaGetSymbolAddress((void**)&z1,   g_z1);
    cudaGetSymbolAddress((void**)&z2,   g_z2);

    float* embPtr;
    float* logitsPtr;
    if ((long)out_size >= (long)n * 144) {
        embPtr = out;
        logitsPtr = out + (size_t)n * 128;
    } else {
        embPtr = embS;
        logitsPtr = out;
    }

    gat_layer(x, 64, W1, as1, ad1, b1, ei, n, e, h, agg, as_, ad_, den, tmp);
    gat_layer(tmp, 128, W2, as2, ad2, b2, ei, n, e, h, agg, as_, ad_, den, embPtr);

    unsigned gy128 = (n + 127) / 128;
    k_gemm_tc<<<dim3(4, gy128), 256>>>(embPtr, lw1, lb1, z1, n, 512, 128, 1);
    k_gemm_tc<<<dim3(2, gy128), 256>>>(z1, lw2, lb2, z2, n, 256, 512, 1);
    k_gemm<<<dim3(1, (n + 63) / 64), 256>>>(z2, lw3, lb3, logitsPtr, n, 16, 256, 0);
}

// round 4
// speedup vs baseline: 1.7056x; 1.1898x over previous
#include <cuda_runtime.h>
#include <math.h>

#define NMAX 50000
#define EMAX 1600000

// ---------------- scratch (device globals; no allocations allowed) ----------
__device__ float g_h   [(size_t)NMAX * 128];
__device__ float g_agg [(size_t)NMAX * 128];
__device__ float g_tmp [(size_t)NMAX * 128];
__device__ float g_emb [(size_t)NMAX * 128];
__device__ float g_as  [NMAX * 2];
__device__ float g_ad  [NMAX * 2];
__device__ float g_den [NMAX * 2];
__device__ float g_z1  [(size_t)NMAX * 512];
__device__ float g_z2  [(size_t)NMAX * 256];

__device__ __forceinline__ float leaky(float v) { return v >= 0.f ? v : 0.2f * v; }

__device__ __forceinline__ unsigned f2tf32(float f) {
    unsigned r;
    asm("cvt.rna.tf32.f32 %0, %1;" : "=r"(r) : "f"(f));
    return r;
}

// ================= tensor-core tf32 GEMM, cp.async double-buffered ==========
// C[M,N] = act(A[M,K] @ B[K,N] + bias). BM=128, BN=128, BK=16.
// 256 threads = 8 warps in 4(m) x 2(n); warp tile 32x64 via m16n8k8 tf32 mma.
// Requires: K % 16 == 0, N % 128 == 0. M tail: A row index clamped (stores guarded).
#define A_STRIDE 20   // floats: 16 + 4 pad; row = 80B (16B-aligned for cp.async)
#define B_STRIDE 136  // floats: 128 + 8 pad; row = 544B (16B-aligned)

__global__ __launch_bounds__(256) void k_gemm_tc(
    const float* __restrict__ A, const float* __restrict__ B,
    const float* __restrict__ bias, float* __restrict__ C,
    int M, int N, int K, int act)
{
    __shared__ float As[2][128 * A_STRIDE];
    __shared__ float Bs[2][16 * B_STRIDE];

    const int tid  = threadIdx.x;
    const int lane = tid & 31;
    const int wid  = tid >> 5;
    const int rb   = blockIdx.y * 128;
    const int cb   = blockIdx.x * 128;
    const int warpM = (wid & 3) * 32;
    const int warpN = (wid >> 2) * 64;

    const int arow = tid >> 2;          // 0..63 (two halves)
    const int acol = (tid & 3) * 4;
    const int brow = tid >> 5;          // 0..7 (two halves)
    const int bcol = (tid & 31) * 4;

    // clamped A row pointers (tail rows read row M-1; their outputs are never stored)
    int ra0 = rb + arow;       if (ra0 >= M) ra0 = M - 1;
    int ra1 = rb + arow + 64;  if (ra1 >= M) ra1 = M - 1;
    const float* pa0 = A + (size_t)ra0 * K + acol;
    const float* pa1 = A + (size_t)ra1 * K + acol;
    const float* pb0 = B + (size_t)brow * N + cb + bcol;
    const float* pb1 = B + (size_t)(brow + 8) * N + cb + bcol;

    unsigned sa0[2], sa1[2], sb0[2], sb1[2];
    #pragma unroll
    for (int s = 0; s < 2; s++) {
        sa0[s] = (unsigned)__cvta_generic_to_shared(&As[s][arow * A_STRIDE + acol]);
        sa1[s] = (unsigned)__cvta_generic_to_shared(&As[s][(arow + 64) * A_STRIDE + acol]);
        sb0[s] = (unsigned)__cvta_generic_to_shared(&Bs[s][brow * B_STRIDE + bcol]);
        sb1[s] = (unsigned)__cvta_generic_to_shared(&Bs[s][(brow + 8) * B_STRIDE + bcol]);
    }

    float acc[2][8][4];
    #pragma unroll
    for (int i = 0; i < 2; i++)
        #pragma unroll
        for (int j = 0; j < 8; j++)
            #pragma unroll
            for (int v = 0; v < 4; v++) acc[i][j][v] = 0.f;

    const int nIt = K >> 4;

    // prologue: stage 0
    asm volatile("cp.async.cg.shared.global [%0], [%1], 16;" :: "r"(sa0[0]), "l"(pa0));
    asm volatile("cp.async.cg.shared.global [%0], [%1], 16;" :: "r"(sa1[0]), "l"(pa1));
    asm volatile("cp.async.cg.shared.global [%0], [%1], 16;" :: "r"(sb0[0]), "l"(pb0));
    asm volatile("cp.async.cg.shared.global [%0], [%1], 16;" :: "r"(sb1[0]), "l"(pb1));
    asm volatile("cp.async.commit_group;");

    for (int it = 0; it < nIt; it++) {
        const int cur = it & 1;
        if (it + 1 < nIt) {
            const int nxt = cur ^ 1;
            int k0 = (it + 1) << 4;
            asm volatile("cp.async.cg.shared.global [%0], [%1], 16;" :: "r"(sa0[nxt]), "l"(pa0 + k0));
            asm volatile("cp.async.cg.shared.global [%0], [%1], 16;" :: "r"(sa1[nxt]), "l"(pa1 + k0));
            asm volatile("cp.async.cg.shared.global [%0], [%1], 16;" :: "r"(sb0[nxt]), "l"(pb0 + (size_t)k0 * N));
            asm volatile("cp.async.cg.shared.global [%0], [%1], 16;" :: "r"(sb1[nxt]), "l"(pb1 + (size_t)k0 * N));
            asm volatile("cp.async.commit_group;");
            asm volatile("cp.async.wait_group 1;");
        } else {
            asm volatile("cp.async.wait_group 0;");
        }
        __syncthreads();

        const float* as = As[cur];
        const float* bs = Bs[cur];
        #pragma unroll
        for (int ks = 0; ks < 2; ks++) {
            unsigned af[2][4];
            #pragma unroll
            for (int mt = 0; mt < 2; mt++) {
                int r0 = warpM + mt * 16 + (lane >> 2);
                int c0 = ks * 8 + (lane & 3);
                af[mt][0] = f2tf32(as[r0 * A_STRIDE + c0]);
                af[mt][1] = f2tf32(as[(r0 + 8) * A_STRIDE + c0]);
                af[mt][2] = f2tf32(as[r0 * A_STRIDE + c0 + 4]);
                af[mt][3] = f2tf32(as[(r0 + 8) * A_STRIDE + c0 + 4]);
            }
            unsigned bf[8][2];
            #pragma unroll
            for (int nt = 0; nt < 8; nt++) {
                int kk = ks * 8 + (lane & 3);
                int nn = warpN + nt * 8 + (lane >> 2);
                bf[nt][0] = f2tf32(bs[kk * B_STRIDE + nn]);
                bf[nt][1] = f2tf32(bs[(kk + 4) * B_STRIDE + nn]);
            }
            #pragma unroll
            for (int mt = 0; mt < 2; mt++)
                #pragma unroll
                for (int nt = 0; nt < 8; nt++) {
                    asm volatile(
                        "mma.sync.aligned.m16n8k8.row.col.f32.tf32.tf32.f32 "
                        "{%0,%1,%2,%3}, {%4,%5,%6,%7}, {%8,%9}, {%0,%1,%2,%3};"
                        : "+f"(acc[mt][nt][0]), "+f"(acc[mt][nt][1]),
                          "+f"(acc[mt][nt][2]), "+f"(acc[mt][nt][3])
                        : "r"(af[mt][0]), "r"(af[mt][1]), "r"(af[mt][2]), "r"(af[mt][3]),
                          "r"(bf[nt][0]), "r"(bf[nt][1]));
                }
        }
        __syncthreads();
    }

    // ---- epilogue: bias + optional relu ----
    #pragma unroll
    for (int mt = 0; mt < 2; mt++) {
        int r0 = rb + warpM + mt * 16 + (lane >> 2);
        #pragma unroll
        for (int nt = 0; nt < 8; nt++) {
            int c0 = cb + warpN + nt * 8 + (lane & 3) * 2;
            float b0 = 0.f, b1 = 0.f;
            if (bias) { b0 = bias[c0]; b1 = bias[c0 + 1]; }
            float v0 = acc[mt][nt][0] + b0;
            float v1 = acc[mt][nt][1] + b1;
            float v2 = acc[mt][nt][2] + b0;
            float v3 = acc[mt][nt][3] + b1;
            if (act) {
                v0 = fmaxf(v0, 0.f); v1 = fmaxf(v1, 0.f);
                v2 = fmaxf(v2, 0.f); v3 = fmaxf(v3, 0.f);
            }
            if (r0 < M) {
                C[(size_t)r0 * N + c0] = v0;
                C[(size_t)r0 * N + c0 + 1] = v1;
            }
            if (r0 + 8 < M) {
                C[(size_t)(r0 + 8) * N + c0] = v2;
                C[(size_t)(r0 + 8) * N + c0 + 1] = v3;
            }
        }
    }
}

// ================= SIMT GEMM (small-N logits only) ===========================
__global__ __launch_bounds__(256) void k_gemm(
    const float* __restrict__ A, const float* __restrict__ B,
    const float* __restrict__ bias, float* __restrict__ C,
    int M, int N, int K, int act)
{
    __shared__ float As[16][68];
    __shared__ float Bs[16][68];
    const int tid = threadIdx.x;
    const int rb = blockIdx.y * 64;
    const int cb = blockIdx.x * 64;
    const int tx = tid & 15;
    const int ty = tid >> 4;
    const int ar = tid >> 2, ak = (tid & 3) * 4;
    const int bk = tid >> 4, bc = (tid & 15) * 4;
    float acc[4][4] = {};

    for (int k0 = 0; k0 < K; k0 += 16) {
        float4 av = make_float4(0.f, 0.f, 0.f, 0.f);
        if (rb + ar < M)
            av = *(const float4*)(A + (size_t)(rb + ar) * K + k0 + ak);
        As[ak + 0][ar] = av.x; As[ak + 1][ar] = av.y;
        As[ak + 2][ar] = av.z; As[ak + 3][ar] = av.w;

        float4 bv = make_float4(0.f, 0.f, 0.f, 0.f);
        if (cb + bc < N)
            bv = *(const float4*)(B + (size_t)(k0 + bk) * N + cb + bc);
        Bs[bk][bc + 0] = bv.x; Bs[bk][bc + 1] = bv.y;
        Bs[bk][bc + 2] = bv.z; Bs[bk][bc + 3] = bv.w;
        __syncthreads();

        #pragma unroll
        for (int k = 0; k < 16; k++) {
            float4 a4 = *(const float4*)&As[k][ty * 4];
            float4 b4 = *(const float4*)&Bs[k][tx * 4];
            float a[4] = {a4.x, a4.y, a4.z, a4.w};
            float b[4] = {b4.x, b4.y, b4.z, b4.w};
            #pragma unroll
            for (int i = 0; i < 4; i++)
                #pragma unroll
                for (int j = 0; j < 4; j++)
                    acc[i][j] = fmaf(a[i], b[j], acc[i][j]);
        }
        __syncthreads();
    }

    #pragma unroll
    for (int i = 0; i < 4; i++) {
        int r = rb + ty * 4 + i;
        if (r >= M) continue;
        #pragma unroll
        for (int j = 0; j < 4; j++) {
            int c = cb + tx * 4 + j;
            if (c >= N) continue;
            float v = acc[i][j];
            if (bias) v += bias[c];
            if (act)  v = fmaxf(v, 0.f);
            C[(size_t)r * N + c] = v;
        }
    }
}

// ---------------- fused per-node pass: alpha dots + self-loop init -----------
// warp per node. lanes 0-15: head 0, lanes 16-31: head 1; each lane owns 4 floats.
// Computes as/ad (stored), den := exp(leaky(as+ad)) (self loop),
// agg := exp(self) * h  (unnormalized self-loop message).
__global__ __launch_bounds__(256) void k_node_fused(
    const float* __restrict__ h, const float* __restrict__ a_src,
    const float* __restrict__ a_dst, float* __restrict__ as_,
    float* __restrict__ ad_, float* __restrict__ den,
    float* __restrict__ agg, int n)
{
    int w = (blockIdx.x * blockDim.x + threadIdx.x) >> 5;
    int lane = threadIdx.x & 31;
    if (w >= n) return;
    int hd = lane >> 4;

    float4 hv = ((const float4*)(h + (size_t)w * 128))[lane];
    float4 sv = ((const float4*)a_src)[lane];   // a_src laid out [2][64] = 32 float4
    float4 dv = ((const float4*)a_dst)[lane];

    float sa = hv.x * sv.x + hv.y * sv.y + hv.z * sv.z + hv.w * sv.w;
    float sd = hv.x * dv.x + hv.y * dv.y + hv.z * dv.z + hv.w * dv.w;
    // reduce within each 16-lane half
    #pragma unroll
    for (int m = 8; m > 0; m >>= 1) {
        sa += __shfl_xor_sync(0xffffffffu, sa, m);
        sd += __shfl_xor_sync(0xffffffffu, sd, m);
    }
    // lanes 0 and 16 hold head results
    float wself = expf(leaky(sa + sd));
    if ((lane & 15) == 0) {
        as_[w * 2 + hd] = sa;
        ad_[w * 2 + hd] = sd;
        den[w * 2 + hd] = wself;
    }
    // broadcast self weight within each half
    wself = __shfl_sync(0xffffffffu, wself, hd << 4);
    ((float4*)(agg + (size_t)w * 128))[lane] =
        make_float4(hv.x * wself, hv.y * wself, hv.z * wself, hv.w * wself);
}

// ---------------- edge pass: unnormalized message + denom scatter ------------
// warp per edge; red.v4 message into agg, red.v2 exp weight into den.
__global__ __launch_bounds__(256) void k_edge_msg(
    const int* __restrict__ ei, const float* __restrict__ h,
    const float* __restrict__ as_, const float* __restrict__ ad_,
    float* __restrict__ den, float* __restrict__ agg, int nE)
{
    int w = (blockIdx.x * blockDim.x + threadIdx.x) >> 5;
    int lane = threadIdx.x & 31;
    if (w >= nE) return;
    int s = ei[w], d = ei[nE + w];
    int hd = lane >> 4;
    float e = leaky(as_[s * 2 + hd] + ad_[d * 2 + hd]);
    float wgt = expf(e);
    float4 hv = *(const float4*)(h + (size_t)s * 128 + lane * 4);
    float* p = agg + (size_t)d * 128 + lane * 4;
    asm volatile("red.global.add.v4.f32 [%0], {%1,%2,%3,%4};"
                 :: "l"(p), "f"(hv.x * wgt), "f"(hv.y * wgt),
                    "f"(hv.z * wgt), "f"(hv.w * wgt)
                 : "memory");
    float w1 = __shfl_sync(0xffffffffu, wgt, 16);
    if (lane == 0)
        asm volatile("red.global.add.v2.f32 [%0], {%1,%2};"
                     :: "l"(den + d * 2), "f"(wgt), "f"(w1) : "memory");
}

// ---------------- per-node: normalize + bias + relu --------------------------
__global__ __launch_bounds__(256) void k_node_out(
    const float* __restrict__ agg, const float* __restrict__ den,
    const float* __restrict__ bias, float* __restrict__ out, int n)
{
    int idx = blockIdx.x * blockDim.x + threadIdx.x;
    if (idx >= n * 32) return;
    int node = idx >> 5, c4 = idx & 31;
    int hd = c4 >> 4;
    float inv = 1.f / (den[node * 2 + hd] + 1e-16f);
    float4 v = ((const float4*)agg)[idx];
    float4 b = ((const float4*)bias)[c4];
    v.x = fmaxf(v.x * inv + b.x, 0.f);
    v.y = fmaxf(v.y * inv + b.y, 0.f);
    v.z = fmaxf(v.z * inv + b.z, 0.f);
    v.w = fmaxf(v.w * inv + b.w, 0.f);
    ((float4*)out)[idx] = v;
}

// ---------------- launch ------------------------------------------------------
static void gat_layer(const float* xin, int inK,
                      const float* W, const float* a_s, const float* a_d,
                      const float* b, const int* ei, int n, int e,
                      float* h, float* agg,
                      float* as_, float* ad_, float* den,
                      float* out)
{
    k_gemm_tc<<<dim3(1, (n + 127) / 128), 256>>>(xin, W, nullptr, h, n, 128, inK, 0);
    k_node_fused<<<(n * 32 + 255) / 256, 256>>>(h, a_s, a_d, as_, ad_, den, agg, n);
    long ethreads = (long)e * 32;
    k_edge_msg<<<(unsigned)((ethreads + 255) / 256), 256>>>(ei, h, as_, ad_, den, agg, e);
    k_node_out<<<(n * 32 + 255) / 256, 256>>>(agg, den, b, out, n);
}

extern "C" void kernel_launch(void* const* d_in, const int* in_sizes, int n_in,
                              void* d_out, int out_size)
{
    const float* x   = (const float*)d_in[0];
    const int*   ei  = (const int*)  d_in[1];
    const float* W1  = (const float*)d_in[2];
    const float* as1 = (const float*)d_in[3];
    const float* ad1 = (const float*)d_in[4];
    const float* b1  = (const float*)d_in[5];
    const float* W2  = (const float*)d_in[6];
    const float* as2 = (const float*)d_in[7];
    const float* ad2 = (const float*)d_in[8];
    const float* b2  = (const float*)d_in[9];
    const float* lw1 = (const float*)d_in[10];
    const float* lb1 = (const float*)d_in[11];
    const float* lw2 = (const float*)d_in[12];
    const float* lb2 = (const float*)d_in[13];
    const float* lw3 = (const float*)d_in[14];
    const float* lb3 = (const float*)d_in[15];
    float* out = (float*)d_out;

    int n = in_sizes[0] / 64;
    int e = in_sizes[1] / 2;

    float *h, *agg, *tmp, *embS, *as_, *ad_, *den, *z1, *z2;
    cudaGetSymbolAddress((void**)&h,    g_h);
    cudaGetSymbolAddress((void**)&agg,  g_agg);
    cudaGetSymbolAddress((void**)&tmp,  g_tmp);
    cudaGetSymbolAddress((void**)&embS, g_emb);
    cudaGetSymbolAddress((void**)&as_,  g_as);
    cudaGetSymbolAddress((void**)&ad_,  g_ad);
    cudaGetSymbolAddress((void**)&den,  g_den);
    cudaGetSymbolAddress((void**)&z1,   g_z1);
    cudaGetSymbolAddress((void**)&z2,   g_z2);

    float* embPtr;
    float* logitsPtr;
    if ((long)out_size >= (long)n * 144) {
        embPtr = out;
        logitsPtr = out + (size_t)n * 128;
    } else {
        embPtr = embS;
        logitsPtr = out;
    }

    gat_layer(x, 64, W1, as1, ad1, b1, ei, n, e, h, agg, as_, ad_, den, tmp);
    gat_layer(tmp, 128, W2, as2, ad2, b2, ei, n, e, h, agg, as_, ad_, den, embPtr);

    unsigned gy128 = (n + 127) / 128;
    k_gemm_tc<<<dim3(4, gy128), 256>>>(embPtr, lw1, lb1, z1, n, 512, 128, 1);
    k_gemm_tc<<<dim3(2, gy128), 256>>>(z1, lw2, lb2, z2, n, 256, 512, 1);
    k_gemm<<<dim3(1, (n + 63) / 64), 256>>>(z2, lw3, lb3, logitsPtr, n, 16, 256, 0);
}

// round 5
// speedup vs baseline: 2.5607x; 1.5014x over previous
#include <cuda_runtime.h>
#include <math.h>

#define NMAX 50000
#define EMAX 1600000
#define SCAN_BLK 512

// ---------------- scratch (device globals; no allocations allowed) ----------
__device__ float g_h   [(size_t)NMAX * 128];
__device__ float g_tmp [(size_t)NMAX * 128];
__device__ float g_emb [(size_t)NMAX * 128];
__device__ float g_as  [NMAX * 2];
__device__ float g_ad  [NMAX * 2];
__device__ float g_z1  [(size_t)NMAX * 512];
__device__ float g_z2  [(size_t)NMAX * 256];
// CSR scratch
__device__ int g_deg   [NMAX];
__device__ int g_incl  [NMAX];
__device__ int g_bsums [1024];
__device__ int g_rowptr[NMAX + 1];
__device__ int g_cursor[NMAX];
__device__ int g_csrc  [EMAX];

__device__ __forceinline__ float leaky(float v) { return v >= 0.f ? v : 0.2f * v; }

__device__ __forceinline__ unsigned f2tf32(float f) {
    unsigned r;
    asm("cvt.rna.tf32.f32 %0, %1;" : "=r"(r) : "f"(f));
    return r;
}

// ================= tensor-core tf32 GEMM, cp.async double-buffered ==========
#define A_STRIDE 20
#define B_STRIDE 136

__global__ __launch_bounds__(256) void k_gemm_tc(
    const float* __restrict__ A, const float* __restrict__ B,
    const float* __restrict__ bias, float* __restrict__ C,
    int M, int N, int K, int act)
{
    __shared__ float As[2][128 * A_STRIDE];
    __shared__ float Bs[2][16 * B_STRIDE];

    const int tid  = threadIdx.x;
    const int lane = tid & 31;
    const int wid  = tid >> 5;
    const int rb   = blockIdx.y * 128;
    const int cb   = blockIdx.x * 128;
    const int warpM = (wid & 3) * 32;
    const int warpN = (wid >> 2) * 64;

    const int arow = tid >> 2;
    const int acol = (tid & 3) * 4;
    const int brow = tid >> 5;
    const int bcol = (tid & 31) * 4;

    int ra0 = rb + arow;       if (ra0 >= M) ra0 = M - 1;
    int ra1 = rb + arow + 64;  if (ra1 >= M) ra1 = M - 1;
    const float* pa0 = A + (size_t)ra0 * K + acol;
    const float* pa1 = A + (size_t)ra1 * K + acol;
    const float* pb0 = B + (size_t)brow * N + cb + bcol;
    const float* pb1 = B + (size_t)(brow + 8) * N + cb + bcol;

    unsigned sa0[2], sa1[2], sb0[2], sb1[2];
    #pragma unroll
    for (int s = 0; s < 2; s++) {
        sa0[s] = (unsigned)__cvta_generic_to_shared(&As[s][arow * A_STRIDE + acol]);
        sa1[s] = (unsigned)__cvta_generic_to_shared(&As[s][(arow + 64) * A_STRIDE + acol]);
        sb0[s] = (unsigned)__cvta_generic_to_shared(&Bs[s][brow * B_STRIDE + bcol]);
        sb1[s] = (unsigned)__cvta_generic_to_shared(&Bs[s][(brow + 8) * B_STRIDE + bcol]);
    }

    float acc[2][8][4];
    #pragma unroll
    for (int i = 0; i < 2; i++)
        #pragma unroll
        for (int j = 0; j < 8; j++)
            #pragma unroll
            for (int v = 0; v < 4; v++) acc[i][j][v] = 0.f;

    const int nIt = K >> 4;

    asm volatile("cp.async.cg.shared.global [%0], [%1], 16;" :: "r"(sa0[0]), "l"(pa0));
    asm volatile("cp.async.cg.shared.global [%0], [%1], 16;" :: "r"(sa1[0]), "l"(pa1));
    asm volatile("cp.async.cg.shared.global [%0], [%1], 16;" :: "r"(sb0[0]), "l"(pb0));
    asm volatile("cp.async.cg.shared.global [%0], [%1], 16;" :: "r"(sb1[0]), "l"(pb1));
    asm volatile("cp.async.commit_group;");

    for (int it = 0; it < nIt; it++) {
        const int cur = it & 1;
        if (it + 1 < nIt) {
            const int nxt = cur ^ 1;
            int k0 = (it + 1) << 4;
            asm volatile("cp.async.cg.shared.global [%0], [%1], 16;" :: "r"(sa0[nxt]), "l"(pa0 + k0));
            asm volatile("cp.async.cg.shared.global [%0], [%1], 16;" :: "r"(sa1[nxt]), "l"(pa1 + k0));
            asm volatile("cp.async.cg.shared.global [%0], [%1], 16;" :: "r"(sb0[nxt]), "l"(pb0 + (size_t)k0 * N));
            asm volatile("cp.async.cg.shared.global [%0], [%1], 16;" :: "r"(sb1[nxt]), "l"(pb1 + (size_t)k0 * N));
            asm volatile("cp.async.commit_group;");
            asm volatile("cp.async.wait_group 1;");
        } else {
            asm volatile("cp.async.wait_group 0;");
        }
        __syncthreads();

        const float* as = As[cur];
        const float* bs = Bs[cur];
        #pragma unroll
        for (int ks = 0; ks < 2; ks++) {
            unsigned af[2][4];
            #pragma unroll
            for (int mt = 0; mt < 2; mt++) {
                int r0 = warpM + mt * 16 + (lane >> 2);
                int c0 = ks * 8 + (lane & 3);
                af[mt][0] = f2tf32(as[r0 * A_STRIDE + c0]);
                af[mt][1] = f2tf32(as[(r0 + 8) * A_STRIDE + c0]);
                af[mt][2] = f2tf32(as[r0 * A_STRIDE + c0 + 4]);
                af[mt][3] = f2tf32(as[(r0 + 8) * A_STRIDE + c0 + 4]);
            }
            unsigned bf[8][2];
            #pragma unroll
            for (int nt = 0; nt < 8; nt++) {
                int kk = ks * 8 + (lane & 3);
                int nn = warpN + nt * 8 + (lane >> 2);
                bf[nt][0] = f2tf32(bs[kk * B_STRIDE + nn]);
                bf[nt][1] = f2tf32(bs[(kk + 4) * B_STRIDE + nn]);
            }
            #pragma unroll
            for (int mt = 0; mt < 2; mt++)
                #pragma unroll
                for (int nt = 0; nt < 8; nt++) {
                    asm volatile(
                        "mma.sync.aligned.m16n8k8.row.col.f32.tf32.tf32.f32 "
                        "{%0,%1,%2,%3}, {%4,%5,%6,%7}, {%8,%9}, {%0,%1,%2,%3};"
                        : "+f"(acc[mt][nt][0]), "+f"(acc[mt][nt][1]),
                          "+f"(acc[mt][nt][2]), "+f"(acc[mt][nt][3])
                        : "r"(af[mt][0]), "r"(af[mt][1]), "r"(af[mt][2]), "r"(af[mt][3]),
                          "r"(bf[nt][0]), "r"(bf[nt][1]));
                }
        }
        __syncthreads();
    }

    #pragma unroll
    for (int mt = 0; mt < 2; mt++) {
        int r0 = rb + warpM + mt * 16 + (lane >> 2);
        #pragma unroll
        for (int nt = 0; nt < 8; nt++) {
            int c0 = cb + warpN + nt * 8 + (lane & 3) * 2;
            float b0 = 0.f, b1 = 0.f;
            if (bias) { b0 = bias[c0]; b1 = bias[c0 + 1]; }
            float v0 = acc[mt][nt][0] + b0;
            float v1 = acc[mt][nt][1] + b1;
            float v2 = acc[mt][nt][2] + b0;
            float v3 = acc[mt][nt][3] + b1;
            if (act) {
                v0 = fmaxf(v0, 0.f); v1 = fmaxf(v1, 0.f);
                v2 = fmaxf(v2, 0.f); v3 = fmaxf(v3, 0.f);
            }
            if (r0 < M) {
                C[(size_t)r0 * N + c0] = v0;
                C[(size_t)r0 * N + c0 + 1] = v1;
            }
            if (r0 + 8 < M) {
                C[(size_t)(r0 + 8) * N + c0] = v2;
                C[(size_t)(r0 + 8) * N + c0 + 1] = v3;
            }
        }
    }
}

// ================= SIMT GEMM (small-N logits only) ===========================
__global__ __launch_bounds__(256) void k_gemm(
    const float* __restrict__ A, const float* __restrict__ B,
    const float* __restrict__ bias, float* __restrict__ C,
    int M, int N, int K, int act)
{
    __shared__ float As[16][68];
    __shared__ float Bs[16][68];
    const int tid = threadIdx.x;
    const int rb = blockIdx.y * 64;
    const int cb = blockIdx.x * 64;
    const int tx = tid & 15;
    const int ty = tid >> 4;
    const int ar = tid >> 2, ak = (tid & 3) * 4;
    const int bk = tid >> 4, bc = (tid & 15) * 4;
    float acc[4][4] = {};

    for (int k0 = 0; k0 < K; k0 += 16) {
        float4 av = make_float4(0.f, 0.f, 0.f, 0.f);
        if (rb + ar < M)
            av = *(const float4*)(A + (size_t)(rb + ar) * K + k0 + ak);
        As[ak + 0][ar] = av.x; As[ak + 1][ar] = av.y;
        As[ak + 2][ar] = av.z; As[ak + 3][ar] = av.w;

        float4 bv = make_float4(0.f, 0.f, 0.f, 0.f);
        if (cb + bc < N)
            bv = *(const float4*)(B + (size_t)(k0 + bk) * N + cb + bc);
        Bs[bk][bc + 0] = bv.x; Bs[bk][bc + 1] = bv.y;
        Bs[bk][bc + 2] = bv.z; Bs[bk][bc + 3] = bv.w;
        __syncthreads();

        #pragma unroll
        for (int k = 0; k < 16; k++) {
            float4 a4 = *(const float4*)&As[k][ty * 4];
            float4 b4 = *(const float4*)&Bs[k][tx * 4];
            float a[4] = {a4.x, a4.y, a4.z, a4.w};
            float b[4] = {b4.x, b4.y, b4.z, b4.w};
            #pragma unroll
            for (int i = 0; i < 4; i++)
                #pragma unroll
                for (int j = 0; j < 4; j++)
                    acc[i][j] = fmaf(a[i], b[j], acc[i][j]);
        }
        __syncthreads();
    }

    #pragma unroll
    for (int i = 0; i < 4; i++) {
        int r = rb + ty * 4 + i;
        if (r >= M) continue;
        #pragma unroll
        for (int j = 0; j < 4; j++) {
            int c = cb + tx * 4 + j;
            if (c >= N) continue;
            float v = acc[i][j];
            if (bias) v += bias[c];
            if (act)  v = fmaxf(v, 0.f);
            C[(size_t)r * N + c] = v;
        }
    }
}

// ================= CSR construction ==========================================
__global__ __launch_bounds__(256) void k_zero(int* p, int n) {
    int i = blockIdx.x * blockDim.x + threadIdx.x;
    if (i < n) p[i] = 0;
}
__global__ __launch_bounds__(256) void k_hist(const int* __restrict__ ei, int* deg, int nE) {
    int e = blockIdx.x * blockDim.x + threadIdx.x;
    if (e < nE) atomicAdd(&deg[ei[nE + e]], 1);
}
// per-block inclusive scan
__global__ __launch_bounds__(SCAN_BLK) void k_scan1(
    const int* __restrict__ deg, int* incl, int* bsums, int n)
{
    __shared__ int sh[SCAN_BLK];
    int i = blockIdx.x * SCAN_BLK + threadIdx.x;
    int v = (i < n) ? deg[i] : 0;
    sh[threadIdx.x] = v;
    __syncthreads();
    for (int off = 1; off < SCAN_BLK; off <<= 1) {
        int t = (threadIdx.x >= off) ? sh[threadIdx.x - off] : 0;
        __syncthreads();
        sh[threadIdx.x] += t;
        __syncthreads();
    }
    if (i < n) incl[i] = sh[threadIdx.x];
    if (threadIdx.x == SCAN_BLK - 1) bsums[blockIdx.x] = sh[SCAN_BLK - 1];
}
// single-block inclusive scan of block sums (nb <= 1024)
__global__ __launch_bounds__(1024) void k_scan2(int* bsums, int nb) {
    __shared__ int sh[1024];
    int i = threadIdx.x;
    sh[i] = (i < nb) ? bsums[i] : 0;
    __syncthreads();
    for (int off = 1; off < 1024; off <<= 1) {
        int t = (i >= off) ? sh[i - off] : 0;
        __syncthreads();
        sh[i] += t;
        __syncthreads();
    }
    if (i < nb) bsums[i] = sh[i];
}
__global__ __launch_bounds__(SCAN_BLK) void k_scan3(
    const int* __restrict__ incl, const int* __restrict__ bsums,
    const int* __restrict__ deg, int* rowptr, int* cursor, int n)
{
    int i = blockIdx.x * SCAN_BLK + threadIdx.x;
    if (i >= n) return;
    int off = (blockIdx.x > 0) ? bsums[blockIdx.x - 1] : 0;
    int inc = incl[i] + off;
    rowptr[i + 1] = inc;
    cursor[i] = inc - deg[i];
    if (i == 0) rowptr[0] = 0;
}
__global__ __launch_bounds__(256) void k_scatter(
    const int* __restrict__ ei, int* cursor, int* csrc, int nE)
{
    int e = blockIdx.x * blockDim.x + threadIdx.x;
    if (e >= nE) return;
    int pos = atomicAdd(&cursor[ei[nE + e]], 1);
    csrc[pos] = ei[e];
}

// ---------------- per-node attention dot products (warp per node) ------------
__global__ __launch_bounds__(256) void k_node_alpha(
    const float* __restrict__ h, const float* __restrict__ a_src,
    const float* __restrict__ a_dst, float* __restrict__ as_,
    float* __restrict__ ad_, int n)
{
    int w = (blockIdx.x * blockDim.x + threadIdx.x) >> 5;
    int lane = threadIdx.x & 31;
    if (w >= n) return;
    int hd = lane >> 4;

    float4 hv = ((const float4*)(h + (size_t)w * 128))[lane];
    float4 sv = ((const float4*)a_src)[lane];
    float4 dv = ((const float4*)a_dst)[lane];

    float sa = hv.x * sv.x + hv.y * sv.y + hv.z * sv.z + hv.w * sv.w;
    float sd = hv.x * dv.x + hv.y * dv.y + hv.z * dv.z + hv.w * dv.w;
    #pragma unroll
    for (int m = 8; m > 0; m >>= 1) {
        sa += __shfl_xor_sync(0xffffffffu, sa, m);
        sd += __shfl_xor_sync(0xffffffffu, sd, m);
    }
    if ((lane & 15) == 0) {
        as_[w * 2 + hd] = sa;
        ad_[w * 2 + hd] = sd;
    }
}

// ---------------- gather aggregation: warp per dst node ----------------------
// Accumulates exp(e)*h[src] and denominator in registers (no atomics),
// adds self loop, normalizes, bias + relu, writes layer output once.
__global__ __launch_bounds__(256) void k_gather(
    const int* __restrict__ rowptr, const int* __restrict__ csrc,
    const float* __restrict__ h, const float* __restrict__ as_,
    const float* __restrict__ ad_, const float* __restrict__ bias,
    float* __restrict__ out, int n)
{
    int w = (blockIdx.x * blockDim.x + threadIdx.x) >> 5;
    int lane = threadIdx.x & 31;
    if (w >= n) return;
    int hd = lane >> 4;

    float add = ad_[w * 2 + hd];
    float wself = expf(leaky(as_[w * 2 + hd] + add));
    float4 hv = ((const float4*)(h + (size_t)w * 128))[lane];
    float4 acc = make_float4(hv.x * wself, hv.y * wself, hv.z * wself, hv.w * wself);
    float den = wself;

    int j = rowptr[w], end = rowptr[w + 1];
    for (; j + 1 < end; j += 2) {
        int s0 = csrc[j], s1 = csrc[j + 1];
        float w0 = expf(leaky(as_[s0 * 2 + hd] + add));
        float w1 = expf(leaky(as_[s1 * 2 + hd] + add));
        float4 h0 = ((const float4*)(h + (size_t)s0 * 128))[lane];
        float4 h1 = ((const float4*)(h + (size_t)s1 * 128))[lane];
        acc.x += w0 * h0.x + w1 * h1.x;
        acc.y += w0 * h0.y + w1 * h1.y;
        acc.z += w0 * h0.z + w1 * h1.z;
        acc.w += w0 * h0.w + w1 * h1.w;
        den += w0 + w1;
    }
    if (j < end) {
        int s0 = csrc[j];
        float w0 = expf(leaky(as_[s0 * 2 + hd] + add));
        float4 h0 = ((const float4*)(h + (size_t)s0 * 128))[lane];
        acc.x += w0 * h0.x; acc.y += w0 * h0.y;
        acc.z += w0 * h0.z; acc.w += w0 * h0.w;
        den += w0;
    }

    float inv = 1.f / (den + 1e-16f);
    float4 b = ((const float4*)bias)[lane];
    float4 o;
    o.x = fmaxf(acc.x * inv + b.x, 0.f);
    o.y = fmaxf(acc.y * inv + b.y, 0.f);
    o.z = fmaxf(acc.z * inv + b.z, 0.f);
    o.w = fmaxf(acc.w * inv + b.w, 0.f);
    ((float4*)(out + (size_t)w * 128))[lane] = o;
}

// ---------------- launch ------------------------------------------------------
static void gat_layer(const float* xin, int inK,
                      const float* W, const float* a_s, const float* a_d,
                      const float* b, int n,
                      const int* rowptr, const int* csrc,
                      float* h, float* as_, float* ad_, float* out)
{
    k_gemm_tc<<<dim3(1, (n + 127) / 128), 256>>>(xin, W, nullptr, h, n, 128, inK, 0);
    k_node_alpha<<<(n * 32 + 255) / 256, 256>>>(h, a_s, a_d, as_, ad_, n);
    k_gather<<<(n * 32 + 255) / 256, 256>>>(rowptr, csrc, h, as_, ad_, b, out, n);
}

extern "C" void kernel_launch(void* const* d_in, const int* in_sizes, int n_in,
                              void* d_out, int out_size)
{
    const float* x   = (const float*)d_in[0];
    const int*   ei  = (const int*)  d_in[1];
    const float* W1  = (const float*)d_in[2];
    const float* as1 = (const float*)d_in[3];
    const float* ad1 = (const float*)d_in[4];
    const float* b1  = (const float*)d_in[5];
    const float* W2  = (const float*)d_in[6];
    const float* as2 = (const float*)d_in[7];
    const float* ad2 = (const float*)d_in[8];
    const float* b2  = (const float*)d_in[9];
    const float* lw1 = (const float*)d_in[10];
    const float* lb1 = (const float*)d_in[11];
    const float* lw2 = (const float*)d_in[12];
    const float* lb2 = (const float*)d_in[13];
    const float* lw3 = (const float*)d_in[14];
    const float* lb3 = (const float*)d_in[15];
    float* out = (float*)d_out;

    int n = in_sizes[0] / 64;
    int e = in_sizes[1] / 2;

    float *h, *tmp, *embS, *as_, *ad_, *z1, *z2;
    int *deg, *incl, *bsums, *rowptr, *cursor, *csrc;
    cudaGetSymbolAddress((void**)&h,    g_h);
    cudaGetSymbolAddress((void**)&tmp,  g_tmp);
    cudaGetSymbolAddress((void**)&embS, g_emb);
    cudaGetSymbolAddress((void**)&as_,  g_as);
    cudaGetSymbolAddress((void**)&ad_,  g_ad);
    cudaGetSymbolAddress((void**)&z1,   g_z1);
    cudaGetSymbolAddress((void**)&z2,   g_z2);
    cudaGetSymbolAddress((void**)&deg,    g_deg);
    cudaGetSymbolAddress((void**)&incl,   g_incl);
    cudaGetSymbolAddress((void**)&bsums,  g_bsums);
    cudaGetSymbolAddress((void**)&rowptr, g_rowptr);
    cudaGetSymbolAddress((void**)&cursor, g_cursor);
    cudaGetSymbolAddress((void**)&csrc,   g_csrc);

    float* embPtr;
    float* logitsPtr;
    if ((long)out_size >= (long)n * 144) {
        embPtr = out;
        logitsPtr = out + (size_t)n * 128;
    } else {
        embPtr = embS;
        logitsPtr = out;
    }

    // ---- build CSR by destination (used by both layers) ----
    int nscan = (n + SCAN_BLK - 1) / SCAN_BLK;
    k_zero<<<(n + 255) / 256, 256>>>(deg, n);
    k_hist<<<(e + 255) / 256, 256>>>(ei, deg, e);
    k_scan1<<<nscan, SCAN_BLK>>>(deg, incl, bsums, n);
    k_scan2<<<1, 1024>>>(bsums, nscan);
    k_scan3<<<nscan, SCAN_BLK>>>(incl, bsums, deg, rowptr, cursor, n);
    k_scatter<<<(e + 255) / 256, 256>>>(ei, cursor, csrc, e);

    // ---- GAT layers ----
    gat_layer(x, 64, W1, as1, ad1, b1, n, rowptr, csrc, h, as_, ad_, tmp);
    gat_layer(tmp, 128, W2, as2, ad2, b2, n, rowptr, csrc, h, as_, ad_, embPtr);

    // ---- MLP head ----
    unsigned gy128 = (n + 127) / 128;
    k_gemm_tc<<<dim3(4, gy128), 256>>>(embPtr, lw1, lb1, z1, n, 512, 128, 1);
    k_gemm_tc<<<dim3(2, gy128), 256>>>(z1, lw2, lb2, z2, n, 256, 512, 1);
    k_gemm<<<dim3(1, (n + 63) / 64), 256>>>(z2, lw3, lb3, logitsPtr, n, 16, 256, 0);
}

// round 6
// speedup vs baseline: 2.6015x; 1.0159x over previous
#include <cuda_runtime.h>
#include <math.h>

#define NMAX 50000
#define EMAX 1600000
#define SCAN_BLK 512

// ---------------- scratch (device globals; no allocations allowed) ----------
__device__ float g_h   [(size_t)NMAX * 128];
__device__ float g_tmp [(size_t)NMAX * 128];
__device__ float g_emb [(size_t)NMAX * 128];
__device__ float g_xr  [(size_t)NMAX * 64];    // tf32-rounded x
__device__ float g_as  [NMAX * 2];
__device__ float g_ad  [NMAX * 2];
__device__ float g_z1  [(size_t)NMAX * 512];
__device__ float g_z2  [(size_t)NMAX * 256];
// tf32-rounded weights
__device__ float g_w1r [64 * 128];
__device__ float g_w2r [128 * 128];
__device__ float g_lw1r[128 * 512];
__device__ float g_lw2r[512 * 256];
// CSR scratch
__device__ int g_deg   [NMAX];
__device__ int g_incl  [NMAX];
__device__ int g_bsums [1024];
__device__ int g_rowptr[NMAX + 1];
__device__ int g_cursor[NMAX];
__device__ int g_csrc  [EMAX];

__device__ __forceinline__ float leaky(float v) { return v >= 0.f ? v : 0.2f * v; }

__device__ __forceinline__ unsigned f2tf32(float f) {
    unsigned r;
    asm("cvt.rna.tf32.f32 %0, %1;" : "=r"(r) : "f"(f));
    return r;
}
__device__ __forceinline__ float rnd32(float f) { return __uint_as_float(f2tf32(f)); }

// ---------------- tf32 pre-rounding passes -----------------------------------
__global__ __launch_bounds__(256) void k_round4(
    const float* __restrict__ src, float* __restrict__ dst, int n4)
{
    int i = blockIdx.x * blockDim.x + threadIdx.x;
    if (i >= n4) return;
    float4 v = ((const float4*)src)[i];
    v.x = rnd32(v.x); v.y = rnd32(v.y); v.z = rnd32(v.z); v.w = rnd32(v.w);
    ((float4*)dst)[i] = v;
}
// all four weight matrices in one launch (segmented)
__global__ __launch_bounds__(256) void k_round_w(
    const float* __restrict__ w1, float* __restrict__ w1r,
    const float* __restrict__ w2, float* __restrict__ w2r,
    const float* __restrict__ l1, float* __restrict__ l1r,
    const float* __restrict__ l2, float* __restrict__ l2r)
{
    const int n1 = 64 * 128, n2 = 128 * 128, n3 = 128 * 512, n4 = 512 * 256;
    int i = blockIdx.x * blockDim.x + threadIdx.x;
    if (i < n1) w1r[i] = rnd32(w1[i]);
    else if (i < n1 + n2) w2r[i - n1] = rnd32(w2[i - n1]);
    else if (i < n1 + n2 + n3) l1r[i - n1 - n2] = rnd32(l1[i - n1 - n2]);
    else if (i < n1 + n2 + n3 + n4) l2r[i - n1 - n2 - n3] = rnd32(l2[i - n1 - n2 - n3]);
}

// ================= tensor-core tf32 GEMM, cp.async double-buffered ==========
// Operands assumed pre-rounded to tf32 unless cvtA (then A frags are converted).
#define A_STRIDE 20
#define B_STRIDE 136

__global__ __launch_bounds__(256, 2) void k_gemm_tc(
    const float* __restrict__ A, const float* __restrict__ B,
    const float* __restrict__ bias, float* __restrict__ C,
    int M, int N, int K, int act, int rndOut, int cvtA)
{
    __shared__ float As[2][128 * A_STRIDE];
    __shared__ float Bs[2][16 * B_STRIDE];

    const int tid  = threadIdx.x;
    const int lane = tid & 31;
    const int wid  = tid >> 5;
    const int rb   = blockIdx.y * 128;
    const int cb   = blockIdx.x * 128;
    const int warpM = (wid & 3) * 32;
    const int warpN = (wid >> 2) * 64;

    const int arow = tid >> 2;
    const int acol = (tid & 3) * 4;
    const int brow = tid >> 5;
    const int bcol = (tid & 31) * 4;

    int ra0 = rb + arow;       if (ra0 >= M) ra0 = M - 1;
    int ra1 = rb + arow + 64;  if (ra1 >= M) ra1 = M - 1;
    const float* pa0 = A + (size_t)ra0 * K + acol;
    const float* pa1 = A + (size_t)ra1 * K + acol;
    const float* pb0 = B + (size_t)brow * N + cb + bcol;
    const float* pb1 = B + (size_t)(brow + 8) * N + cb + bcol;

    unsigned sa0[2], sa1[2], sb0[2], sb1[2];
    #pragma unroll
    for (int s = 0; s < 2; s++) {
        sa0[s] = (unsigned)__cvta_generic_to_shared(&As[s][arow * A_STRIDE + acol]);
        sa1[s] = (unsigned)__cvta_generic_to_shared(&As[s][(arow + 64) * A_STRIDE + acol]);
        sb0[s] = (unsigned)__cvta_generic_to_shared(&Bs[s][brow * B_STRIDE + bcol]);
        sb1[s] = (unsigned)__cvta_generic_to_shared(&Bs[s][(brow + 8) * B_STRIDE + bcol]);
    }

    float acc[2][8][4];
    #pragma unroll
    for (int i = 0; i < 2; i++)
        #pragma unroll
        for (int j = 0; j < 8; j++)
            #pragma unroll
            for (int v = 0; v < 4; v++) acc[i][j][v] = 0.f;

    const int nIt = K >> 4;

    asm volatile("cp.async.cg.shared.global [%0], [%1], 16;" :: "r"(sa0[0]), "l"(pa0));
    asm volatile("cp.async.cg.shared.global [%0], [%1], 16;" :: "r"(sa1[0]), "l"(pa1));
    asm volatile("cp.async.cg.shared.global [%0], [%1], 16;" :: "r"(sb0[0]), "l"(pb0));
    asm volatile("cp.async.cg.shared.global [%0], [%1], 16;" :: "r"(sb1[0]), "l"(pb1));
    asm volatile("cp.async.commit_group;");

    for (int it = 0; it < nIt; it++) {
        const int cur = it & 1;
        if (it + 1 < nIt) {
            const int nxt = cur ^ 1;
            int k0 = (it + 1) << 4;
            asm volatile("cp.async.cg.shared.global [%0], [%1], 16;" :: "r"(sa0[nxt]), "l"(pa0 + k0));
            asm volatile("cp.async.cg.shared.global [%0], [%1], 16;" :: "r"(sa1[nxt]), "l"(pa1 + k0));
            asm volatile("cp.async.cg.shared.global [%0], [%1], 16;" :: "r"(sb0[nxt]), "l"(pb0 + (size_t)k0 * N));
            asm volatile("cp.async.cg.shared.global [%0], [%1], 16;" :: "r"(sb1[nxt]), "l"(pb1 + (size_t)k0 * N));
            asm volatile("cp.async.commit_group;");
            asm volatile("cp.async.wait_group 1;");
        } else {
            asm volatile("cp.async.wait_group 0;");
        }
        __syncthreads();

        const float* as = As[cur];
        const float* bs = Bs[cur];
        #pragma unroll
        for (int ks = 0; ks < 2; ks++) {
            unsigned af[2][4];
            #pragma unroll
            for (int mt = 0; mt < 2; mt++) {
                int r0 = warpM + mt * 16 + (lane >> 2);
                int c0 = ks * 8 + (lane & 3);
                if (cvtA) {
                    af[mt][0] = f2tf32(as[r0 * A_STRIDE + c0]);
                    af[mt][1] = f2tf32(as[(r0 + 8) * A_STRIDE + c0]);
                    af[mt][2] = f2tf32(as[r0 * A_STRIDE + c0 + 4]);
                    af[mt][3] = f2tf32(as[(r0 + 8) * A_STRIDE + c0 + 4]);
                } else {
                    af[mt][0] = __float_as_uint(as[r0 * A_STRIDE + c0]);
                    af[mt][1] = __float_as_uint(as[(r0 + 8) * A_STRIDE + c0]);
                    af[mt][2] = __float_as_uint(as[r0 * A_STRIDE + c0 + 4]);
                    af[mt][3] = __float_as_uint(as[(r0 + 8) * A_STRIDE + c0 + 4]);
                }
            }
            unsigned bf[8][2];
            #pragma unroll
            for (int nt = 0; nt < 8; nt++) {
                int kk = ks * 8 + (lane & 3);
                int nn = warpN + nt * 8 + (lane >> 2);
                bf[nt][0] = __float_as_uint(bs[kk * B_STRIDE + nn]);
                bf[nt][1] = __float_as_uint(bs[(kk + 4) * B_STRIDE + nn]);
            }
            #pragma unroll
            for (int mt = 0; mt < 2; mt++)
                #pragma unroll
                for (int nt = 0; nt < 8; nt++) {
                    asm volatile(
                        "mma.sync.aligned.m16n8k8.row.col.f32.tf32.tf32.f32 "
                        "{%0,%1,%2,%3}, {%4,%5,%6,%7}, {%8,%9}, {%0,%1,%2,%3};"
                        : "+f"(acc[mt][nt][0]), "+f"(acc[mt][nt][1]),
                          "+f"(acc[mt][nt][2]), "+f"(acc[mt][nt][3])
                        : "r"(af[mt][0]), "r"(af[mt][1]), "r"(af[mt][2]), "r"(af[mt][3]),
                          "r"(bf[nt][0]), "r"(bf[nt][1]));
                }
        }
        __syncthreads();
    }

    #pragma unroll
    for (int mt = 0; mt < 2; mt++) {
        int r0 = rb + warpM + mt * 16 + (lane >> 2);
        #pragma unroll
        for (int nt = 0; nt < 8; nt++) {
            int c0 = cb + warpN + nt * 8 + (lane & 3) * 2;
            float b0 = 0.f, b1 = 0.f;
            if (bias) { b0 = bias[c0]; b1 = bias[c0 + 1]; }
            float v0 = acc[mt][nt][0] + b0;
            float v1 = acc[mt][nt][1] + b1;
            float v2 = acc[mt][nt][2] + b0;
            float v3 = acc[mt][nt][3] + b1;
            if (act) {
                v0 = fmaxf(v0, 0.f); v1 = fmaxf(v1, 0.f);
                v2 = fmaxf(v2, 0.f); v3 = fmaxf(v3, 0.f);
            }
            if (rndOut) {
                v0 = rnd32(v0); v1 = rnd32(v1); v2 = rnd32(v2); v3 = rnd32(v3);
            }
            if (r0 < M) {
                C[(size_t)r0 * N + c0] = v0;
                C[(size_t)r0 * N + c0 + 1] = v1;
            }
            if (r0 + 8 < M) {
                C[(size_t)(r0 + 8) * N + c0] = v2;
                C[(size_t)(r0 + 8) * N + c0 + 1] = v3;
            }
        }
    }
}

// ================= SIMT GEMM (small-N logits only) ===========================
__global__ __launch_bounds__(256) void k_gemm(
    const float* __restrict__ A, const float* __restrict__ B,
    const float* __restrict__ bias, float* __restrict__ C,
    int M, int N, int K, int act)
{
    __shared__ float As[16][68];
    __shared__ float Bs[16][68];
    const int tid = threadIdx.x;
    const int rb = blockIdx.y * 64;
    const int cb = blockIdx.x * 64;
    const int tx = tid & 15;
    const int ty = tid >> 4;
    const int ar = tid >> 2, ak = (tid & 3) * 4;
    const int bk = tid >> 4, bc = (tid & 15) * 4;
    float acc[4][4] = {};

    for (int k0 = 0; k0 < K; k0 += 16) {
        float4 av = make_float4(0.f, 0.f, 0.f, 0.f);
        if (rb + ar < M)
            av = *(const float4*)(A + (size_t)(rb + ar) * K + k0 + ak);
        As[ak + 0][ar] = av.x; As[ak + 1][ar] = av.y;
        As[ak + 2][ar] = av.z; As[ak + 3][ar] = av.w;

        float4 bv = make_float4(0.f, 0.f, 0.f, 0.f);
        if (cb + bc < N)
            bv = *(const float4*)(B + (size_t)(k0 + bk) * N + cb + bc);
        Bs[bk][bc + 0] = bv.x; Bs[bk][bc + 1] = bv.y;
        Bs[bk][bc + 2] = bv.z; Bs[bk][bc + 3] = bv.w;
        __syncthreads();

        #pragma unroll
        for (int k = 0; k < 16; k++) {
            float4 a4 = *(const float4*)&As[k][ty * 4];
            float4 b4 = *(const float4*)&Bs[k][tx * 4];
            float a[4] = {a4.x, a4.y, a4.z, a4.w};
            float b[4] = {b4.x, b4.y, b4.z, b4.w};
            #pragma unroll
            for (int i = 0; i < 4; i++)
                #pragma unroll
                for (int j = 0; j < 4; j++)
                    acc[i][j] = fmaf(a[i], b[j], acc[i][j]);
        }
        __syncthreads();
    }

    #pragma unroll
    for (int i = 0; i < 4; i++) {
        int r = rb + ty * 4 + i;
        if (r >= M) continue;
        #pragma unroll
        for (int j = 0; j < 4; j++) {
            int c = cb + tx * 4 + j;
            if (c >= N) continue;
            float v = acc[i][j];
            if (bias) v += bias[c];
            if (act)  v = fmaxf(v, 0.f);
            C[(size_t)r * N + c] = v;
        }
    }
}

// ================= CSR construction ==========================================
__global__ __launch_bounds__(256) void k_zero(int* p, int n) {
    int i = blockIdx.x * blockDim.x + threadIdx.x;
    if (i < n) p[i] = 0;
}
__global__ __launch_bounds__(256) void k_hist(const int* __restrict__ ei, int* deg, int nE) {
    int e = blockIdx.x * blockDim.x + threadIdx.x;
    if (e < nE) atomicAdd(&deg[ei[nE + e]], 1);
}
__global__ __launch_bounds__(SCAN_BLK) void k_scan1(
    const int* __restrict__ deg, int* incl, int* bsums, int n)
{
    __shared__ int sh[SCAN_BLK];
    int i = blockIdx.x * SCAN_BLK + threadIdx.x;
    int v = (i < n) ? deg[i] : 0;
    sh[threadIdx.x] = v;
    __syncthreads();
    for (int off = 1; off < SCAN_BLK; off <<= 1) {
        int t = (threadIdx.x >= off) ? sh[threadIdx.x - off] : 0;
        __syncthreads();
        sh[threadIdx.x] += t;
        __syncthreads();
    }
    if (i < n) incl[i] = sh[threadIdx.x];
    if (threadIdx.x == SCAN_BLK - 1) bsums[blockIdx.x] = sh[SCAN_BLK - 1];
}
__global__ __launch_bounds__(1024) void k_scan2(int* bsums, int nb) {
    __shared__ int sh[1024];
    int i = threadIdx.x;
    sh[i] = (i < nb) ? bsums[i] : 0;
    __syncthreads();
    for (int off = 1; off < 1024; off <<= 1) {
        int t = (i >= off) ? sh[i - off] : 0;
        __syncthreads();
        sh[i] += t;
        __syncthreads();
    }
    if (i < nb) bsums[i] = sh[i];
}
__global__ __launch_bounds__(SCAN_BLK) void k_scan3(
    const int* __restrict__ incl, const int* __restrict__ bsums,
    const int* __restrict__ deg, int* rowptr, int* cursor, int n)
{
    int i = blockIdx.x * SCAN_BLK + threadIdx.x;
    if (i >= n) return;
    int off = (blockIdx.x > 0) ? bsums[blockIdx.x - 1] : 0;
    int inc = incl[i] + off;
    rowptr[i + 1] = inc;
    cursor[i] = inc - deg[i];
    if (i == 0) rowptr[0] = 0;
}
__global__ __launch_bounds__(256) void k_scatter(
    const int* __restrict__ ei, int* cursor, int* csrc, int nE)
{
    int e = blockIdx.x * blockDim.x + threadIdx.x;
    if (e >= nE) return;
    int pos = atomicAdd(&cursor[ei[nE + e]], 1);
    csrc[pos] = ei[e];
}

// ---------------- per-node attention dot products (warp per node) ------------
__global__ __launch_bounds__(256) void k_node_alpha(
    const float* __restrict__ h, const float* __restrict__ a_src,
    const float* __restrict__ a_dst, float* __restrict__ as_,
    float* __restrict__ ad_, int n)
{
    int w = (blockIdx.x * blockDim.x + threadIdx.x) >> 5;
    int lane = threadIdx.x & 31;
    if (w >= n) return;
    int hd = lane >> 4;

    float4 hv = ((const float4*)(h + (size_t)w * 128))[lane];
    float4 sv = ((const float4*)a_src)[lane];
    float4 dv = ((const float4*)a_dst)[lane];

    float sa = hv.x * sv.x + hv.y * sv.y + hv.z * sv.z + hv.w * sv.w;
    float sd = hv.x * dv.x + hv.y * dv.y + hv.z * dv.z + hv.w * dv.w;
    #pragma unroll
    for (int m = 8; m > 0; m >>= 1) {
        sa += __shfl_xor_sync(0xffffffffu, sa, m);
        sd += __shfl_xor_sync(0xffffffffu, sd, m);
    }
    if ((lane & 15) == 0) {
        as_[w * 2 + hd] = sa;
        ad_[w * 2 + hd] = sd;
    }
}

// ---------------- gather aggregation: warp per dst node ----------------------
__global__ __launch_bounds__(256) void k_gather(
    const int* __restrict__ rowptr, const int* __restrict__ csrc,
    const float* __restrict__ h, const float* __restrict__ as_,
    const float* __restrict__ ad_, const float* __restrict__ bias,
    float* __restrict__ out, int n, int rndOut)
{
    int w = (blockIdx.x * blockDim.x + threadIdx.x) >> 5;
    int lane = threadIdx.x & 31;
    if (w >= n) return;
    int hd = lane >> 4;

    float add = ad_[w * 2 + hd];
    float wself = expf(leaky(as_[w * 2 + hd] + add));
    float4 hv = ((const float4*)(h + (size_t)w * 128))[lane];
    float4 acc = make_float4(hv.x * wself, hv.y * wself, hv.z * wself, hv.w * wself);
    float den = wself;

    int j = rowptr[w], end = rowptr[w + 1];
    for (; j + 1 < end; j += 2) {
        int s0 = csrc[j], s1 = csrc[j + 1];
        float w0 = expf(leaky(as_[s0 * 2 + hd] + add));
        float w1 = expf(leaky(as_[s1 * 2 + hd] + add));
        float4 h0 = ((const float4*)(h + (size_t)s0 * 128))[lane];
        float4 h1 = ((const float4*)(h + (size_t)s1 * 128))[lane];
        acc.x += w0 * h0.x + w1 * h1.x;
        acc.y += w0 * h0.y + w1 * h1.y;
        acc.z += w0 * h0.z + w1 * h1.z;
        acc.w += w0 * h0.w + w1 * h1.w;
        den += w0 + w1;
    }
    if (j < end) {
        int s0 = csrc[j];
        float w0 = expf(leaky(as_[s0 * 2 + hd] + add));
        float4 h0 = ((const float4*)(h + (size_t)s0 * 128))[lane];
        acc.x += w0 * h0.x; acc.y += w0 * h0.y;
        acc.z += w0 * h0.z; acc.w += w0 * h0.w;
        den += w0;
    }

    float inv = 1.f / (den + 1e-16f);
    float4 b = ((const float4*)bias)[lane];
    float4 o;
    o.x = fmaxf(acc.x * inv + b.x, 0.f);
    o.y = fmaxf(acc.y * inv + b.y, 0.f);
    o.z = fmaxf(acc.z * inv + b.z, 0.f);
    o.w = fmaxf(acc.w * inv + b.w, 0.f);
    if (rndOut) {
        o.x = rnd32(o.x); o.y = rnd32(o.y);
        o.z = rnd32(o.z); o.w = rnd32(o.w);
    }
    ((float4*)(out + (size_t)w * 128))[lane] = o;
}

// ---------------- launch ------------------------------------------------------
extern "C" void kernel_launch(void* const* d_in, const int* in_sizes, int n_in,
                              void* d_out, int out_size)
{
    const float* x   = (const float*)d_in[0];
    const int*   ei  = (const int*)  d_in[1];
    const float* W1  = (const float*)d_in[2];
    const float* as1 = (const float*)d_in[3];
    const float* ad1 = (const float*)d_in[4];
    const float* b1  = (const float*)d_in[5];
    const float* W2  = (const float*)d_in[6];
    const float* as2 = (const float*)d_in[7];
    const float* ad2 = (const float*)d_in[8];
    const float* b2  = (const float*)d_in[9];
    const float* lw1 = (const float*)d_in[10];
    const float* lb1 = (const float*)d_in[11];
    const float* lw2 = (const float*)d_in[12];
    const float* lb2 = (const float*)d_in[13];
    const float* lw3 = (const float*)d_in[14];
    const float* lb3 = (const float*)d_in[15];
    float* out = (float*)d_out;

    int n = in_sizes[0] / 64;
    int e = in_sizes[1] / 2;

    float *h, *tmp, *embS, *xr, *as_, *ad_, *z1, *z2;
    float *w1r, *w2r, *lw1r, *lw2r;
    int *deg, *incl, *bsums, *rowptr, *cursor, *csrc;
    cudaGetSymbolAddress((void**)&h,    g_h);
    cudaGetSymbolAddress((void**)&tmp,  g_tmp);
    cudaGetSymbolAddress((void**)&embS, g_emb);
    cudaGetSymbolAddress((void**)&xr,   g_xr);
    cudaGetSymbolAddress((void**)&as_,  g_as);
    cudaGetSymbolAddress((void**)&ad_,  g_ad);
    cudaGetSymbolAddress((void**)&z1,   g_z1);
    cudaGetSymbolAddress((void**)&z2,   g_z2);
    cudaGetSymbolAddress((void**)&w1r,  g_w1r);
    cudaGetSymbolAddress((void**)&w2r,  g_w2r);
    cudaGetSymbolAddress((void**)&lw1r, g_lw1r);
    cudaGetSymbolAddress((void**)&lw2r, g_lw2r);
    cudaGetSymbolAddress((void**)&deg,    g_deg);
    cudaGetSymbolAddress((void**)&incl,   g_incl);
    cudaGetSymbolAddress((void**)&bsums,  g_bsums);
    cudaGetSymbolAddress((void**)&rowptr, g_rowptr);
    cudaGetSymbolAddress((void**)&cursor, g_cursor);
    cudaGetSymbolAddress((void**)&csrc,   g_csrc);

    float* embPtr;
    float* logitsPtr;
    if ((long)out_size >= (long)n * 144) {
        embPtr = out;
        logitsPtr = out + (size_t)n * 128;
    } else {
        embPtr = embS;
        logitsPtr = out;
    }

    // ---- pre-round GEMM operands to tf32 ----
    int nx4 = n * 64 / 4;
    k_round4<<<(nx4 + 255) / 256, 256>>>(x, xr, nx4);
    const int wtot = 64*128 + 128*128 + 128*512 + 512*256;
    k_round_w<<<(wtot + 255) / 256, 256>>>(W1, w1r, W2, w2r, lw1, lw1r, lw2, lw2r);

    // ---- build CSR by destination ----
    int nscan = (n + SCAN_BLK - 1) / SCAN_BLK;
    k_zero<<<(n + 255) / 256, 256>>>(deg, n);
    k_hist<<<(e + 255) / 256, 256>>>(ei, deg, e);
    k_scan1<<<nscan, SCAN_BLK>>>(deg, incl, bsums, n);
    k_scan2<<<1, 1024>>>(bsums, nscan);
    k_scan3<<<nscan, SCAN_BLK>>>(incl, bsums, deg, rowptr, cursor, n);
    k_scatter<<<(e + 255) / 256, 256>>>(ei, cursor, csrc, e);

    unsigned gy128 = (n + 127) / 128;
    int nodeGrid = (n * 32 + 255) / 256;

    // ---- GAT layer 1 ----
    k_gemm_tc<<<dim3(1, gy128), 256>>>(xr, w1r, nullptr, h, n, 128, 64, 0, 0, 0);
    k_node_alpha<<<nodeGrid, 256>>>(h, as1, ad1, as_, ad_, n);
    k_gather<<<nodeGrid, 256>>>(rowptr, csrc, h, as_, ad_, b1, tmp, n, 1);

    // ---- GAT layer 2 ----
    k_gemm_tc<<<dim3(1, gy128), 256>>>(tmp, w2r, nullptr, h, n, 128, 128, 0, 0, 0);
    k_node_alpha<<<nodeGrid, 256>>>(h, as2, ad2, as_, ad_, n);
    k_gather<<<nodeGrid, 256>>>(rowptr, csrc, h, as_, ad_, b2, embPtr, n, 0);

    // ---- MLP head ----
    k_gemm_tc<<<dim3(4, gy128), 256>>>(embPtr, lw1r, lb1, z1, n, 512, 128, 1, 1, 1);
    k_gemm_tc<<<dim3(2, gy128), 256>>>(z1, lw2r, lb2, z2, n, 256, 512, 1, 0, 0);
    k_gemm<<<dim3(1, (n + 63) / 64), 256>>>(z2, lw3, lb3, logitsPtr, n, 16, 256, 0);
}